// round 6
// baseline (speedup 1.0000x reference)
#include <cuda_runtime.h>
#include <math_constants.h>
#include <math.h>

#define Bsz   4
#define SEQ   2048
#define Dm    512
#define NH    8
#define Dh    64
#define TOPK  10
#define BH    (Bsz*NH)                 // 32
#define CTX_ELEMS ((size_t)Bsz*SEQ*Dm) // 4,194,304
#define FULLM 0xffffffffu

typedef unsigned long long ull;

// Scratch for projected Q/K/V in head-major layout [B*H][S][64]
__device__ float g_Q[BH*SEQ*Dh];
__device__ float g_K[BH*SEQ*Dh];
__device__ float g_V[BH*SEQ*Dh];

// ---- packed f32x2 helpers (Blackwell FFMA2 path; each lane = IEEE fp32 fma) ----
__device__ __forceinline__ ull pk2(float lo, float hi) {
    ull r; asm("mov.b64 %0, {%1, %2};" : "=l"(r) : "f"(lo), "f"(hi)); return r;
}
__device__ __forceinline__ ull fma2(ull a, ull b, ull c) {
    ull d; asm("fma.rn.f32x2 %0, %1, %2, %3;" : "=l"(d) : "l"(a), "l"(b), "l"(c)); return d;
}
__device__ __forceinline__ void unpk2(ull v, float& lo, float& hi) {
    asm("mov.b64 {%0, %1}, %2;" : "=f"(lo), "=f"(hi) : "l"(v));
}

// ---------------------------------------------------------------------------
// QKV projection (unchanged from passing round 4): single in-order FMA chain
// over k per output, packed over row pairs.
// ---------------------------------------------------------------------------
__global__ __launch_bounds__(256) void qkv_gemm(
    const float* __restrict__ x,
    const float* __restrict__ Wq, const float* __restrict__ bq,
    const float* __restrict__ Wk, const float* __restrict__ bk,
    const float* __restrict__ Wv, const float* __restrict__ bv)
{
    const float* W; const float* bias; float* out;
    if (blockIdx.z == 0)      { W = Wq; bias = bq; out = g_Q; }
    else if (blockIdx.z == 1) { W = Wk; bias = bk; out = g_K; }
    else                      { W = Wv; bias = bv; out = g_V; }

    __shared__ float xs[32*132];
    __shared__ float ws[32*68];

    int tid = threadIdx.x;
    int tx = tid & 15, ty = tid >> 4;
    int m0 = blockIdx.y * 128;
    int n0 = blockIdx.x * 64;
    int head = blockIdx.x;

    ull acc2[4][4];
    #pragma unroll
    for (int i = 0; i < 4; i++)
        #pragma unroll
        for (int j = 0; j < 4; j++) acc2[i][j] = 0ull;

    for (int kt = 0; kt < Dm; kt += 32) {
        #pragma unroll
        for (int i = 0; i < 16; i++) {
            int idx = i*256 + tid;
            int row = idx >> 5, kc = idx & 31;
            xs[kc*132 + row] = x[(size_t)(m0+row)*Dm + kt + kc];
        }
        #pragma unroll
        for (int i = 0; i < 8; i++) {
            int idx = i*256 + tid;
            int col = idx >> 5, kc = idx & 31;
            ws[kc*68 + col] = W[(size_t)(n0+col)*Dm + kt + kc];
        }
        __syncthreads();
        #pragma unroll 8
        for (int kk = 0; kk < 32; kk++) {
            ulonglong2 a01 = *(const ulonglong2*)&xs[kk*132 + ty*8];
            ulonglong2 a23 = *(const ulonglong2*)&xs[kk*132 + ty*8 + 4];
            float4 b4 = *(const float4*)&ws[kk*68 + tx*4];
            ull ap[4] = {a01.x, a01.y, a23.x, a23.y};
            ull bp[4] = {pk2(b4.x,b4.x), pk2(b4.y,b4.y),
                         pk2(b4.z,b4.z), pk2(b4.w,b4.w)};
            #pragma unroll
            for (int i = 0; i < 4; i++)
                #pragma unroll
                for (int j = 0; j < 4; j++)
                    acc2[i][j] = fma2(ap[i], bp[j], acc2[i][j]);
        }
        __syncthreads();
    }

    #pragma unroll
    for (int i = 0; i < 8; i++) {
        int m  = m0 + ty*8 + i;
        int b_ = m >> 11;
        int s_ = m & 2047;
        float* orow = out + ((size_t)(b_*NH + head)*SEQ + s_)*Dh + tx*4;
        #pragma unroll
        for (int j = 0; j < 4; j++) {
            float lo, hi; unpk2(acc2[i>>1][j], lo, hi);
            float v = (i & 1) ? hi : lo;
            orow[j] = v + bias[n0 + tx*4 + j];
        }
    }
}

// ---------------------------------------------------------------------------
// Fused attention. Top-10 list lives in registers, warp-distributed:
// lane t (t<10) of warp w holds rank-t (value,index) for each of its 8 rows.
// Insert = popc(ballot) position + shfl_up shift; same ordering semantics as
// the smem sorted-insert (strictly-greater admits, insert after equals).
// ---------------------------------------------------------------------------
__global__ __launch_bounds__(256) void attn_kernel(float* __restrict__ out)
{
    extern __shared__ char smraw[];
    float4* Ks4 = (float4*)smraw;                 // [16 jj][129]
    float*  Qt  = (float*)(smraw + 16*129*16);    // [64 dd][68]

    const int bh   = blockIdx.x;        // 0..31
    const int q0   = blockIdx.y * 64;
    const int tid  = threadIdx.x;
    const int lane = tid & 31;
    const int w    = tid >> 5;
    const float scale = 0.125f;

    // distributed top-10 lists: lane t = rank t (t<10); others junk (-inf init)
    float lv[8]; int li[8];
    #pragma unroll
    for (int r = 0; r < 8; r++) { lv[r] = -CUDART_INF_F; li[r] = 0; }

    {   // Q transposed into smem: Qt[dd][row] (row pairs contiguous)
        const float* Qg = g_Q + ((size_t)bh*SEQ + q0)*Dh;
        for (int i = tid; i < 64*64; i += 256) {
            int row = i >> 6, dd = i & 63;
            Qt[dd*68 + row] = Qg[row*Dh + dd];
        }
    }
    __syncthreads();

    #pragma unroll 1
    for (int chunk = 0; chunk < 16; chunk++) {
        const float4* Kg4 = (const float4*)(g_K + ((size_t)bh*SEQ + chunk*128)*Dh);
        for (int i = tid; i < 128*16; i += 256) {
            int key = i >> 4, jj = i & 15;
            Ks4[jj*129 + key] = Kg4[i];
        }
        __syncthreads();

        // scores: warp w rows w*8..w*8+7 vs keys c*32+lane; canonical
        // in-order FMA chain over d (jj asc, dd asc), packed per row pair
        ull acc2[4][4];
        #pragma unroll
        for (int rp = 0; rp < 4; rp++)
            #pragma unroll
            for (int c = 0; c < 4; c++) acc2[rp][c] = 0ull;

        #pragma unroll 2
        for (int jj = 0; jj < 16; jj++) {
            float4 kv[4];
            kv[0] = Ks4[jj*129 +       lane];
            kv[1] = Ks4[jj*129 + 32  + lane];
            kv[2] = Ks4[jj*129 + 64  + lane];
            kv[3] = Ks4[jj*129 + 96  + lane];
            #pragma unroll
            for (int dd = 0; dd < 4; dd++) {
                const float* qrow = &Qt[(4*jj + dd)*68 + w*8];
                ulonglong2 qa = *(const ulonglong2*)qrow;
                ulonglong2 qb = *(const ulonglong2*)(qrow + 4);
                ull qp[4] = {qa.x, qa.y, qb.x, qb.y};
                float k0 = dd==0?kv[0].x : dd==1?kv[0].y : dd==2?kv[0].z : kv[0].w;
                float k1 = dd==0?kv[1].x : dd==1?kv[1].y : dd==2?kv[1].z : kv[1].w;
                float k2 = dd==0?kv[2].x : dd==1?kv[2].y : dd==2?kv[2].z : kv[2].w;
                float k3 = dd==0?kv[3].x : dd==1?kv[3].y : dd==2?kv[3].z : kv[3].w;
                ull kp[4] = {pk2(k0,k0), pk2(k1,k1), pk2(k2,k2), pk2(k3,k3)};
                #pragma unroll
                for (int rp = 0; rp < 4; rp++)
                    #pragma unroll
                    for (int c = 0; c < 4; c++)
                        acc2[rp][c] = fma2(qp[rp], kp[c], acc2[rp][c]);
            }
        }

        // top-10 update, row pair at a time (ascending key order preserved:
        // chunk asc, c asc, lane asc within each ballot)
        #pragma unroll
        for (int rp = 0; rp < 4; rp++) {
            float sc[2][4];
            #pragma unroll
            for (int c = 0; c < 4; c++) unpk2(acc2[rp][c], sc[0][c], sc[1][c]);
            #pragma unroll
            for (int h = 0; h < 2; h++) {
                int r = 2*rp + h;
                float v0 = sc[h][0]*scale, v1 = sc[h][1]*scale;
                float v2 = sc[h][2]*scale, v3 = sc[h][3]*scale;
                float thr = __shfl_sync(FULLM, lv[r], 9);
                float mx4 = fmaxf(fmaxf(v0, v1), fmaxf(v2, v3));
                if (!__ballot_sync(FULLM, mx4 > thr)) continue;   // fast skip
                float vc[4] = {v0, v1, v2, v3};
                #pragma unroll
                for (int c = 0; c < 4; c++) {
                    float v = vc[c];
                    int key = chunk*128 + c*32 + lane;
                    unsigned m = __ballot_sync(FULLM, v > thr);
                    while (m) {
                        int src = __ffs(m) - 1; m &= m - 1;
                        float vv = __shfl_sync(FULLM, v, src);
                        int   kk = __shfl_sync(FULLM, key, src);
                        if (vv > thr) {   // uniform across warp
                            unsigned ge = __ballot_sync(FULLM, lv[r] >= vv) & 0x3FFu;
                            int pos = __popc(ge);            // insert after equals
                            float shv = __shfl_up_sync(FULLM, lv[r], 1);
                            int   shi = __shfl_up_sync(FULLM, li[r], 1);
                            if (lane == pos)      { lv[r] = vv;  li[r] = kk;  }
                            else if (lane > pos)  { lv[r] = shv; li[r] = shi; }
                            thr = __shfl_sync(FULLM, lv[r], 9);
                        }
                    }
                }
            }
        }
        __syncthreads();
    }

    // finalize: softmax over top-10 (list in registers), dense row + context
    for (int r = 0; r < 8; r++) {
        int q = q0 + w*8 + r;
        float v = (lane < TOPK) ? lv[r] : -CUDART_INF_F;
        int  ix = li[r];
        float mx = __shfl_sync(FULLM, lv[r], 0);   // rank 0 = max
        float e = (lane < TOPK) ? expf(v - mx) : 0.f;
        float ssum = e;
        #pragma unroll
        for (int off = 16; off > 0; off >>= 1)
            ssum += __shfl_xor_sync(FULLM, ssum, off);
        float p = e / ssum;

        float pw[TOPK]; int iw[TOPK];
        #pragma unroll
        for (int t = 0; t < TOPK; t++) {
            pw[t] = __shfl_sync(FULLM, p,  t);
            iw[t] = __shfl_sync(FULLM, ix, t);
        }

        float c0 = 0.f, c1 = 0.f;
        #pragma unroll
        for (int t = 0; t < TOPK; t++) {
            const float* vp = g_V + ((size_t)bh*SEQ + iw[t])*Dh;
            c0 = fmaf(pw[t], vp[lane],      c0);
            c1 = fmaf(pw[t], vp[lane + 32], c1);
        }
        int b_ = bh >> 3, h_ = bh & 7;
        size_t co = ((size_t)(b_*SEQ + q))*Dm + h_*Dh;
        out[co + lane]      = c0;
        out[co + lane + 32] = c1;

        float4* arow4 = (float4*)(out + CTX_ELEMS + ((size_t)bh*SEQ + q)*SEQ);
        #pragma unroll 4
        for (int st = 0; st < 16; st++) {
            bool any = false;
            #pragma unroll
            for (int t = 0; t < TOPK; t++) any |= ((iw[t] >> 7) == st);
            float4 rv = make_float4(0.f, 0.f, 0.f, 0.f);
            if (any) {
                int cbase = st*128 + lane*4;
                #pragma unroll
                for (int t = 0; t < TOPK; t++) {
                    rv.x = (iw[t] == cbase    ) ? pw[t] : rv.x;
                    rv.y = (iw[t] == cbase + 1) ? pw[t] : rv.y;
                    rv.z = (iw[t] == cbase + 2) ? pw[t] : rv.z;
                    rv.w = (iw[t] == cbase + 3) ? pw[t] : rv.w;
                }
            }
            arow4[st*32 + lane] = rv;
        }
    }
}

// ---------------------------------------------------------------------------
extern "C" void kernel_launch(void* const* d_in, const int* in_sizes, int n_in,
                              void* d_out, int out_size)
{
    const float* x  = (const float*)d_in[0];
    const float* Wq = (const float*)d_in[1];
    const float* bq = (const float*)d_in[2];
    const float* Wk = (const float*)d_in[3];
    const float* bk = (const float*)d_in[4];
    const float* Wv = (const float*)d_in[5];
    const float* bv = (const float*)d_in[6];
    float* out = (float*)d_out;

    const int smem_attn = 16*129*16 + 64*68*4;   // 50,432 B
    cudaFuncSetAttribute(attn_kernel, cudaFuncAttributeMaxDynamicSharedMemorySize, smem_attn);

    qkv_gemm<<<dim3(8, 64, 3), 256>>>(x, Wq, bq, Wk, bk, Wv, bv);
    attn_kernel<<<dim3(BH, SEQ/64), 256, smem_attn>>>(out);
}

// round 9
// speedup vs baseline: 1.5767x; 1.5767x over previous
#include <cuda_runtime.h>
#include <math_constants.h>
#include <math.h>

#define Bsz   4
#define SEQ   2048
#define Dm    512
#define NH    8
#define Dh    64
#define TOPK  10
#define BH    (Bsz*NH)                 // 32
#define CTX_ELEMS ((size_t)Bsz*SEQ*Dm) // 4,194,304
#define FULLM 0xffffffffu

typedef unsigned long long ull;

// Scratch for projected Q/K/V in head-major layout [B*H][S][64]
__device__ float g_Q[BH*SEQ*Dh];
__device__ float g_K[BH*SEQ*Dh];
__device__ float g_V[BH*SEQ*Dh];

// ---- packed f32x2 helpers (Blackwell FFMA2 path; each lane = IEEE fp32 fma) ----
__device__ __forceinline__ ull pk2(float lo, float hi) {
    ull r; asm("mov.b64 %0, {%1, %2};" : "=l"(r) : "f"(lo), "f"(hi)); return r;
}
__device__ __forceinline__ ull fma2(ull a, ull b, ull c) {
    ull d; asm("fma.rn.f32x2 %0, %1, %2, %3;" : "=l"(d) : "l"(a), "l"(b), "l"(c)); return d;
}
__device__ __forceinline__ void unpk2(ull v, float& lo, float& hi) {
    asm("mov.b64 {%0, %1}, %2;" : "=f"(lo), "=f"(hi) : "l"(v));
}

// ---------------------------------------------------------------------------
// QKV projection (unchanged from passing rounds): single in-order FMA chain
// over k per output, packed over row pairs (bit-identical to scalar fmaf).
// ---------------------------------------------------------------------------
__global__ __launch_bounds__(256) void qkv_gemm(
    const float* __restrict__ x,
    const float* __restrict__ Wq, const float* __restrict__ bq,
    const float* __restrict__ Wk, const float* __restrict__ bk,
    const float* __restrict__ Wv, const float* __restrict__ bv)
{
    const float* W; const float* bias; float* out;
    if (blockIdx.z == 0)      { W = Wq; bias = bq; out = g_Q; }
    else if (blockIdx.z == 1) { W = Wk; bias = bk; out = g_K; }
    else                      { W = Wv; bias = bv; out = g_V; }

    __shared__ float xs[32*132];
    __shared__ float ws[32*68];

    int tid = threadIdx.x;
    int tx = tid & 15, ty = tid >> 4;
    int m0 = blockIdx.y * 128;
    int n0 = blockIdx.x * 64;
    int head = blockIdx.x;

    ull acc2[4][4];
    #pragma unroll
    for (int i = 0; i < 4; i++)
        #pragma unroll
        for (int j = 0; j < 4; j++) acc2[i][j] = 0ull;

    for (int kt = 0; kt < Dm; kt += 32) {
        #pragma unroll
        for (int i = 0; i < 16; i++) {
            int idx = i*256 + tid;
            int row = idx >> 5, kc = idx & 31;
            xs[kc*132 + row] = x[(size_t)(m0+row)*Dm + kt + kc];
        }
        #pragma unroll
        for (int i = 0; i < 8; i++) {
            int idx = i*256 + tid;
            int col = idx >> 5, kc = idx & 31;
            ws[kc*68 + col] = W[(size_t)(n0+col)*Dm + kt + kc];
        }
        __syncthreads();
        #pragma unroll 8
        for (int kk = 0; kk < 32; kk++) {
            ulonglong2 a01 = *(const ulonglong2*)&xs[kk*132 + ty*8];
            ulonglong2 a23 = *(const ulonglong2*)&xs[kk*132 + ty*8 + 4];
            float4 b4 = *(const float4*)&ws[kk*68 + tx*4];
            ull ap[4] = {a01.x, a01.y, a23.x, a23.y};
            ull bp[4] = {pk2(b4.x,b4.x), pk2(b4.y,b4.y),
                         pk2(b4.z,b4.z), pk2(b4.w,b4.w)};
            #pragma unroll
            for (int i = 0; i < 4; i++)
                #pragma unroll
                for (int j = 0; j < 4; j++)
                    acc2[i][j] = fma2(ap[i], bp[j], acc2[i][j]);
        }
        __syncthreads();
    }

    #pragma unroll
    for (int i = 0; i < 8; i++) {
        int m  = m0 + ty*8 + i;
        int b_ = m >> 11;
        int s_ = m & 2047;
        float* orow = out + ((size_t)(b_*NH + head)*SEQ + s_)*Dh + tx*4;
        #pragma unroll
        for (int j = 0; j < 4; j++) {
            float lo, hi; unpk2(acc2[i>>1][j], lo, hi);
            float v = (i & 1) ? hi : lo;
            orow[j] = v + bias[n0 + tx*4 + j];
        }
    }
}

// ---------------------------------------------------------------------------
// Fused attention. Top-10 persistent state in SMEM (tval/tidx, stride 12);
// inserts are warp-parallel with TRANSIENT register copies of the list:
// fast-skip ballot vs cached threshold, then load list -> popc-position
// insert via shfl_up -> store back once per (row, chunk).
// Selection semantics identical to all passing rounds (strictly-greater
// admits, insert after equals, ascending chunk/c/lane key order).
// ---------------------------------------------------------------------------
__global__ __launch_bounds__(256, 2) void attn_kernel(float* __restrict__ out)
{
    extern __shared__ char smraw[];
    float4* Ks4  = (float4*)smraw;                              // [16 jj][129]
    float*  Qt   = (float*)(smraw + 16*129*16);                 // [64 dd][68]
    float*  tval = (float*)(smraw + 16*129*16 + 64*68*4);       // [64][12]
    int*    tidx = (int*)  (tval + 64*12);                      // [64][12]

    const int bh   = blockIdx.x;        // 0..31
    const int q0   = blockIdx.y * 64;
    const int tid  = threadIdx.x;
    const int lane = tid & 31;
    const int w    = tid >> 5;
    const float scale = 0.125f;

    for (int i = tid; i < 64*12; i += 256) { tval[i] = -CUDART_INF_F; tidx[i] = 0; }

    float thr[8];                       // cached 10th value per row (8 regs)
    #pragma unroll
    for (int r = 0; r < 8; r++) thr[r] = -CUDART_INF_F;

    {   // Q transposed into smem: Qt[dd][row] (row pairs contiguous)
        const float* Qg = g_Q + ((size_t)bh*SEQ + q0)*Dh;
        for (int i = tid; i < 64*64; i += 256) {
            int row = i >> 6, dd = i & 63;
            Qt[dd*68 + row] = Qg[row*Dh + dd];
        }
    }
    __syncthreads();

    #pragma unroll 1
    for (int chunk = 0; chunk < 16; chunk++) {
        const float4* Kg4 = (const float4*)(g_K + ((size_t)bh*SEQ + chunk*128)*Dh);
        for (int i = tid; i < 128*16; i += 256) {
            int key = i >> 4, jj = i & 15;
            Ks4[jj*129 + key] = Kg4[i];
        }
        __syncthreads();

        // scores: warp w rows w*8..w*8+7 vs keys c*32+lane; canonical
        // in-order FMA chain over d (jj asc, dd asc), packed per row pair
        ull acc2[4][4];
        #pragma unroll
        for (int rp = 0; rp < 4; rp++)
            #pragma unroll
            for (int c = 0; c < 4; c++) acc2[rp][c] = 0ull;

        #pragma unroll 2
        for (int jj = 0; jj < 16; jj++) {
            float4 kv[4];
            kv[0] = Ks4[jj*129 +       lane];
            kv[1] = Ks4[jj*129 + 32  + lane];
            kv[2] = Ks4[jj*129 + 64  + lane];
            kv[3] = Ks4[jj*129 + 96  + lane];
            #pragma unroll
            for (int dd = 0; dd < 4; dd++) {
                const float* qrow = &Qt[(4*jj + dd)*68 + w*8];
                ulonglong2 qa = *(const ulonglong2*)qrow;
                ulonglong2 qb = *(const ulonglong2*)(qrow + 4);
                ull qp[4] = {qa.x, qa.y, qb.x, qb.y};
                float k0 = dd==0?kv[0].x : dd==1?kv[0].y : dd==2?kv[0].z : kv[0].w;
                float k1 = dd==0?kv[1].x : dd==1?kv[1].y : dd==2?kv[1].z : kv[1].w;
                float k2 = dd==0?kv[2].x : dd==1?kv[2].y : dd==2?kv[2].z : kv[2].w;
                float k3 = dd==0?kv[3].x : dd==1?kv[3].y : dd==2?kv[3].z : kv[3].w;
                ull kp[4] = {pk2(k0,k0), pk2(k1,k1), pk2(k2,k2), pk2(k3,k3)};
                #pragma unroll
                for (int rp = 0; rp < 4; rp++)
                    #pragma unroll
                    for (int c = 0; c < 4; c++)
                        acc2[rp][c] = fma2(qp[rp], kp[c], acc2[rp][c]);
            }
        }

        // top-10 update per row: fast-skip, then transient-register insert
        #pragma unroll
        for (int rp = 0; rp < 4; rp++) {
            float sc[2][4];
            #pragma unroll
            for (int c = 0; c < 4; c++) unpk2(acc2[rp][c], sc[0][c], sc[1][c]);
            #pragma unroll
            for (int h = 0; h < 2; h++) {
                const int r = 2*rp + h;
                const int row = w*8 + r;
                float v0 = sc[h][0]*scale, v1 = sc[h][1]*scale;
                float v2 = sc[h][2]*scale, v3 = sc[h][3]*scale;
                float mx4 = fmaxf(fmaxf(v0, v1), fmaxf(v2, v3));
                if (!__ballot_sync(FULLM, mx4 > thr[r])) continue;   // fast skip

                // load list into transient lane registers (lane t = rank t)
                float myv = -CUDART_INF_F; int myi = 0;
                if (lane < TOPK) { myv = tval[row*12 + lane]; myi = tidx[row*12 + lane]; }

                float vc[4] = {v0, v1, v2, v3};
                #pragma unroll
                for (int c = 0; c < 4; c++) {
                    float v = vc[c];
                    int key = chunk*128 + c*32 + lane;
                    unsigned m = __ballot_sync(FULLM, v > thr[r]);
                    while (m) {
                        int src = __ffs(m) - 1; m &= m - 1;
                        float vv = __shfl_sync(FULLM, v, src);
                        int   kk = __shfl_sync(FULLM, key, src);
                        if (vv > thr[r]) {   // uniform across warp
                            unsigned ge = __ballot_sync(FULLM, myv >= vv) & 0x3FFu;
                            int pos = __popc(ge);            // insert after equals
                            float shv = __shfl_up_sync(FULLM, myv, 1);
                            int   shi = __shfl_up_sync(FULLM, myi, 1);
                            if (lane == pos)      { myv = vv;  myi = kk;  }
                            else if (lane > pos)  { myv = shv; myi = shi; }
                            thr[r] = __shfl_sync(FULLM, myv, 9);
                        }
                    }
                }
                if (lane < TOPK) { tval[row*12 + lane] = myv; tidx[row*12 + lane] = myi; }
            }
        }
        __syncthreads();
    }

    // finalize: softmax over top-10, write dense attn row + context
    for (int r = 0; r < 8; r++) {
        int row = w*8 + r;
        int q   = q0 + row;
        float v = (lane < TOPK) ? tval[row*12 + lane] : -CUDART_INF_F;
        int  ix = (lane < TOPK) ? tidx[row*12 + lane] : 0;
        float mx = __shfl_sync(FULLM, v, 0);     // rank 0 = max
        float e = (lane < TOPK) ? expf(v - mx) : 0.f;
        float ssum = e;
        #pragma unroll
        for (int off = 16; off > 0; off >>= 1)
            ssum += __shfl_xor_sync(FULLM, ssum, off);
        float p = e / ssum;

        float pw[TOPK]; int iw[TOPK];
        #pragma unroll
        for (int t = 0; t < TOPK; t++) {
            pw[t] = __shfl_sync(FULLM, p,  t);
            iw[t] = __shfl_sync(FULLM, ix, t);
        }

        float c0 = 0.f, c1 = 0.f;
        #pragma unroll
        for (int t = 0; t < TOPK; t++) {
            const float* vp = g_V + ((size_t)bh*SEQ + iw[t])*Dh;
            c0 = fmaf(pw[t], vp[lane],      c0);
            c1 = fmaf(pw[t], vp[lane + 32], c1);
        }
        int b_ = bh >> 3, h_ = bh & 7;
        size_t co = ((size_t)(b_*SEQ + q))*Dm + h_*Dh;
        out[co + lane]      = c0;
        out[co + lane + 32] = c1;

        float4* arow4 = (float4*)(out + CTX_ELEMS + ((size_t)bh*SEQ + q)*SEQ);
        #pragma unroll 4
        for (int st = 0; st < 16; st++) {
            bool any = false;
            #pragma unroll
            for (int t = 0; t < TOPK; t++) any |= ((iw[t] >> 7) == st);
            float4 rv = make_float4(0.f, 0.f, 0.f, 0.f);
            if (any) {
                int cbase = st*128 + lane*4;
                #pragma unroll
                for (int t = 0; t < TOPK; t++) {
                    rv.x = (iw[t] == cbase    ) ? pw[t] : rv.x;
                    rv.y = (iw[t] == cbase + 1) ? pw[t] : rv.y;
                    rv.z = (iw[t] == cbase + 2) ? pw[t] : rv.z;
                    rv.w = (iw[t] == cbase + 3) ? pw[t] : rv.w;
                }
            }
            arow4[st*32 + lane] = rv;
        }
    }
}

// ---------------------------------------------------------------------------
extern "C" void kernel_launch(void* const* d_in, const int* in_sizes, int n_in,
                              void* d_out, int out_size)
{
    const float* x  = (const float*)d_in[0];
    const float* Wq = (const float*)d_in[1];
    const float* bq = (const float*)d_in[2];
    const float* Wk = (const float*)d_in[3];
    const float* bk = (const float*)d_in[4];
    const float* Wv = (const float*)d_in[5];
    const float* bv = (const float*)d_in[6];
    float* out = (float*)d_out;

    const int smem_attn = 16*129*16 + 64*68*4 + 64*12*4 + 64*12*4; // 56,576 B
    cudaFuncSetAttribute(attn_kernel, cudaFuncAttributeMaxDynamicSharedMemorySize, smem_attn);

    qkv_gemm<<<dim3(8, 64, 3), 256>>>(x, Wq, bq, Wk, bk, Wv, bv);
    attn_kernel<<<dim3(BH, SEQ/64), 256, smem_attn>>>(out);
}